// round 9
// baseline (speedup 1.0000x reference)
#include <cuda_runtime.h>
#include <math_constants.h>

#define NROWS 8192
#define DIM   64
#define KNN   32
#define MOUT  (NROWS - KNN)      // 8160 query rows
#define QT    32                 // queries per block
#define CT    128                // candidate tile rows
#define SX    68                 // smem row stride in floats
#define NTHREADS 256

__device__ float g_sq[NROWS];

__global__ void sq_kernel(const float* __restrict__ X) {
    int i = blockIdx.x * blockDim.x + threadIdx.x;
    if (i < NROWS) {
        const float4* x4 = (const float4*)(X + (size_t)i * DIM);
        float s = 0.f;
        #pragma unroll
        for (int t = 0; t < DIM / 4; ++t) {
            float4 v = x4[t];
            s += v.x * v.x + v.y * v.y + v.z * v.z + v.w * v.w;
        }
        g_sq[i] = s;
    }
}

// XLA-GPU-style row sum-of-squares: t_l = x_l^2 + x_{l+32}^2 (mul/add, no fma),
// then shfl_down-bracketed pairwise tree (+16,+8,+4,+2,+1), done scalar.
__device__ __forceinline__ float sq_tree(const float* __restrict__ c) {
    float t[32];
    #pragma unroll
    for (int l = 0; l < 32; ++l)
        t[l] = __fadd_rn(__fmul_rn(c[l], c[l]), __fmul_rn(c[l + 32], c[l + 32]));
    #pragma unroll
    for (int l = 0; l < 16; ++l) t[l] = __fadd_rn(t[l], t[l + 16]);
    #pragma unroll
    for (int l = 0; l < 8; ++l)  t[l] = __fadd_rn(t[l], t[l + 8]);
    #pragma unroll
    for (int l = 0; l < 4; ++l)  t[l] = __fadd_rn(t[l], t[l + 4]);
    t[0] = __fadd_rn(t[0], t[2]);
    t[1] = __fadd_rn(t[1], t[3]);
    return __fadd_rn(t[0], t[1]);
}

__global__ __launch_bounds__(NTHREADS) void knn_kernel(const float* __restrict__ X,
                                                       void* __restrict__ out, int mode) {
    __shared__ float xs[CT * SX];
    __shared__ float qs[QT * DIM];
    __shared__ float sqc[CT];

    const int tid  = threadIdx.x;
    const int lane = tid & 31;
    const int warp = tid >> 5;
    const int b  = gridDim.x - 1 - blockIdx.x;
    const int qb = KNN + b * QT;

    const float4* X4 = (const float4*)X;

    for (int idx = tid; idx < QT * (DIM / 4); idx += NTHREADS) {
        int row = idx >> 4, c = idx & 15;
        ((float4*)qs)[row * (DIM / 4) + c] = X4[(size_t)(qb + row) * (DIM / 4) + c];
    }

    float sqq[4];
    float ld[4];
    int   li[4];
    #pragma unroll
    for (int w = 0; w < 4; ++w) {
        sqq[w] = g_sq[qb + warp * 4 + w];
        ld[w]  = CUDART_INF_F;
        li[w]  = -1;
    }

    const int cand_end = qb + QT;
    for (int tb = 0; tb < cand_end; tb += CT) {
        __syncthreads();
        for (int idx = tid; idx < CT * (DIM / 4); idx += NTHREADS) {
            int row = idx >> 4, c = idx & 15;
            *(float4*)&xs[row * SX + c * 4] = X4[(size_t)(tb + row) * (DIM / 4) + c];
        }
        if (tid < CT) sqc[tid] = g_sq[tb + tid];
        __syncthreads();

        float acc[4][4];
        #pragma unroll
        for (int w = 0; w < 4; ++w)
            #pragma unroll
            for (int ch = 0; ch < 4; ++ch) acc[w][ch] = 0.f;

        #pragma unroll 4
        for (int d4 = 0; d4 < DIM / 4; ++d4) {
            float4 qv[4], cv[4];
            #pragma unroll
            for (int w = 0; w < 4; ++w)
                qv[w] = *(const float4*)&qs[(warp * 4 + w) * DIM + d4 * 4];
            #pragma unroll
            for (int ch = 0; ch < 4; ++ch)
                cv[ch] = *(const float4*)&xs[(lane + 32 * ch) * SX + d4 * 4];
            #pragma unroll
            for (int w = 0; w < 4; ++w)
                #pragma unroll
                for (int ch = 0; ch < 4; ++ch) {
                    acc[w][ch] = fmaf(qv[w].x, cv[ch].x, acc[w][ch]);
                    acc[w][ch] = fmaf(qv[w].y, cv[ch].y, acc[w][ch]);
                    acc[w][ch] = fmaf(qv[w].z, cv[ch].z, acc[w][ch]);
                    acc[w][ch] = fmaf(qv[w].w, cv[ch].w, acc[w][ch]);
                }
        }

        #pragma unroll
        for (int ch = 0; ch < 4; ++ch) {
            const int   j  = tb + ch * 32 + lane;
            const float sc = sqc[ch * 32 + lane];
            #pragma unroll
            for (int w = 0; w < 4; ++w) {
                const int r = qb + warp * 4 + w;
                float dist = (j < r) ? fmaxf(sqq[w] + sc - 2.f * acc[w][ch], 0.f)
                                     : CUDART_INF_F;
                float kd = __shfl_sync(0xffffffffu, ld[w], 31);
                int   ki = __shfl_sync(0xffffffffu, li[w], 31);
                unsigned hits = __ballot_sync(0xffffffffu,
                                              dist < kd || (dist == kd && j < ki));
                while (hits) {
                    int src = __ffs(hits) - 1;
                    hits &= hits - 1;
                    float dv = __shfl_sync(0xffffffffu, dist, src);
                    int   iv = tb + ch * 32 + src;
                    bool lt  = (ld[w] < dv) || (ld[w] == dv && li[w] < iv);
                    int  pos = __popc(__ballot_sync(0xffffffffu, lt));
                    if (pos < 32) {
                        float pd = __shfl_up_sync(0xffffffffu, ld[w], 1);
                        int   pi = __shfl_up_sync(0xffffffffu, li[w], 1);
                        if (lane == pos)      { ld[w] = dv; li[w] = iv; }
                        else if (lane > pos)  { ld[w] = pd; li[w] = pi; }
                    }
                }
            }
        }
    }

    // ---- phase 2: replicate the reference's rounding structure for the 32
    // survivors: tree-reduced fp32 sq (XLA-GPU row-reduce order) + sequential
    // fp32 FMA dot (cublas per-thread k-order), combined fl(fl(sqr+sqj)-fl(2d)).
    #pragma unroll
    for (int w = 0; w < 4; ++w) {
        int jj = li[w];                                // list always full (r >= KNN)
        const float* qrow = &qs[(warp * 4 + w) * DIM];

        // query sq via same tree (per-query constant; also tightens output 0)
        float qv[DIM];
        #pragma unroll
        for (int t = 0; t < DIM; ++t) qv[t] = qrow[t];
        float sqr = sq_tree(qv);

        // candidate row
        float cv[DIM];
        const float4* crow = X4 + (size_t)jj * (DIM / 4);
        #pragma unroll
        for (int t = 0; t < DIM / 4; ++t) {
            float4 v = __ldg(&crow[t]);
            cv[4 * t + 0] = v.x; cv[4 * t + 1] = v.y;
            cv[4 * t + 2] = v.z; cv[4 * t + 3] = v.w;
        }
        float sqj = sq_tree(cv);

        // sequential fp32 FMA dot, k ascending
        float dot = 0.f;
        #pragma unroll
        for (int t = 0; t < DIM; ++t) dot = __fmaf_rn(qv[t], cv[t], dot);

        float df = fmaxf(__fsub_rn(__fadd_rn(sqr, sqj), __fmul_rn(2.f, dot)), 0.f);

        // bitonic sort across 32 lanes, ascending (df, jj)
        #pragma unroll
        for (int k = 2; k <= 32; k <<= 1) {
            #pragma unroll
            for (int s = k >> 1; s > 0; s >>= 1) {
                float od = __shfl_xor_sync(0xffffffffu, df, s);
                int   oi = __shfl_xor_sync(0xffffffffu, jj, s);
                bool up    = ((lane & k) == 0);
                bool lower = ((lane & s) == 0);
                bool mlt   = (df < od) || (df == od && jj < oi);
                bool take  = (lower == up) ? !mlt : mlt;
                if (take) { df = od; jj = oi; }
            }
        }
        ld[w] = df;
        li[w] = jj;
    }

    #pragma unroll
    for (int w = 0; w < 4; ++w) {
        const int r = qb + warp * 4 + w;
        const size_t m = (size_t)(r - KNN);
        float* of = (float*)out;
        of[m * KNN + lane] = ld[w];
        if (mode == 0) {
            of[(size_t)MOUT * KNN + m * KNN + lane] = (float)li[w];
        } else if (mode == 2) {
            long long* oi = (long long*)((char*)out + (size_t)MOUT * KNN * sizeof(float));
            oi[m * KNN + lane] = (long long)li[w];
        }
    }
}

extern "C" void kernel_launch(void* const* d_in, const int* in_sizes, int n_in,
                              void* d_out, int out_size) {
    const float* X = (const float*)d_in[0];
    for (int i = 0; i < n_in; ++i) {
        if (in_sizes[i] == NROWS * DIM) { X = (const float*)d_in[i]; break; }
    }

    sq_kernel<<<NROWS / 256, 256>>>(X);

    const int MK = MOUT * KNN;
    int mode;
    if (out_size == MK)            mode = 1;
    else if (out_size == 2 * MK)   mode = 0;
    else                           mode = 2;
    knn_kernel<<<MOUT / QT, NTHREADS>>>(X, d_out, mode);
}

// round 10
// speedup vs baseline: 1.0052x; 1.0052x over previous
#include <cuda_runtime.h>
#include <math_constants.h>

#define NROWS 8192
#define DIM   64
#define KNN   32
#define MOUT  (NROWS - KNN)      // 8160 query rows
#define QT    32                 // queries per block (select)
#define CT    128                // candidate tile rows
#define SX    68                 // smem row stride in floats
#define NTHREADS 256
#define RQ    8                  // queries per block (refine)

__device__ float g_sq[NROWS];
__device__ int   g_idx[(size_t)MOUT * KNN];

__global__ void sq_kernel(const float* __restrict__ X) {
    int i = blockIdx.x * blockDim.x + threadIdx.x;
    if (i < NROWS) {
        const float4* x4 = (const float4*)(X + (size_t)i * DIM);
        float s = 0.f;
        #pragma unroll
        for (int t = 0; t < DIM / 4; ++t) {
            float4 v = x4[t];
            s += v.x * v.x + v.y * v.y + v.z * v.z + v.w * v.w;
        }
        g_sq[i] = s;
    }
}

// ---------------- phase 1: top-32 candidate selection ----------------
__global__ __launch_bounds__(NTHREADS, 3) void select_kernel(const float* __restrict__ X) {
    __shared__ float xs[CT * SX];
    __shared__ float qs[QT * DIM];
    __shared__ float sqc[CT];

    const int tid  = threadIdx.x;
    const int lane = tid & 31;
    const int warp = tid >> 5;
    const int b  = gridDim.x - 1 - blockIdx.x;
    const int qb = KNN + b * QT;

    const float4* X4 = (const float4*)X;

    for (int idx = tid; idx < QT * (DIM / 4); idx += NTHREADS) {
        int row = idx >> 4, c = idx & 15;
        ((float4*)qs)[row * (DIM / 4) + c] = X4[(size_t)(qb + row) * (DIM / 4) + c];
    }

    float sqq[4];
    float ld[4];
    int   li[4];
    #pragma unroll
    for (int w = 0; w < 4; ++w) {
        sqq[w] = g_sq[qb + warp * 4 + w];
        ld[w]  = CUDART_INF_F;
        li[w]  = -1;
    }

    const int cand_end = qb + QT;
    for (int tb = 0; tb < cand_end; tb += CT) {
        __syncthreads();
        for (int idx = tid; idx < CT * (DIM / 4); idx += NTHREADS) {
            int row = idx >> 4, c = idx & 15;
            *(float4*)&xs[row * SX + c * 4] = X4[(size_t)(tb + row) * (DIM / 4) + c];
        }
        if (tid < CT) sqc[tid] = g_sq[tb + tid];
        __syncthreads();

        float acc[4][4];
        #pragma unroll
        for (int w = 0; w < 4; ++w)
            #pragma unroll
            for (int ch = 0; ch < 4; ++ch) acc[w][ch] = 0.f;

        #pragma unroll 4
        for (int d4 = 0; d4 < DIM / 4; ++d4) {
            float4 qv[4], cv[4];
            #pragma unroll
            for (int w = 0; w < 4; ++w)
                qv[w] = *(const float4*)&qs[(warp * 4 + w) * DIM + d4 * 4];
            #pragma unroll
            for (int ch = 0; ch < 4; ++ch)
                cv[ch] = *(const float4*)&xs[(lane + 32 * ch) * SX + d4 * 4];
            #pragma unroll
            for (int w = 0; w < 4; ++w)
                #pragma unroll
                for (int ch = 0; ch < 4; ++ch) {
                    acc[w][ch] = fmaf(qv[w].x, cv[ch].x, acc[w][ch]);
                    acc[w][ch] = fmaf(qv[w].y, cv[ch].y, acc[w][ch]);
                    acc[w][ch] = fmaf(qv[w].z, cv[ch].z, acc[w][ch]);
                    acc[w][ch] = fmaf(qv[w].w, cv[ch].w, acc[w][ch]);
                }
        }

        #pragma unroll
        for (int ch = 0; ch < 4; ++ch) {
            const int   j  = tb + ch * 32 + lane;
            const float sc = sqc[ch * 32 + lane];
            #pragma unroll
            for (int w = 0; w < 4; ++w) {
                const int r = qb + warp * 4 + w;
                float dist = (j < r) ? fmaxf(sqq[w] + sc - 2.f * acc[w][ch], 0.f)
                                     : CUDART_INF_F;
                float kd = __shfl_sync(0xffffffffu, ld[w], 31);
                int   ki = __shfl_sync(0xffffffffu, li[w], 31);
                unsigned hits = __ballot_sync(0xffffffffu,
                                              dist < kd || (dist == kd && j < ki));
                while (hits) {
                    int src = __ffs(hits) - 1;
                    hits &= hits - 1;
                    float dv = __shfl_sync(0xffffffffu, dist, src);
                    int   iv = tb + ch * 32 + src;
                    bool lt  = (ld[w] < dv) || (ld[w] == dv && li[w] < iv);
                    int  pos = __popc(__ballot_sync(0xffffffffu, lt));
                    if (pos < 32) {
                        float pd = __shfl_up_sync(0xffffffffu, ld[w], 1);
                        int   pi = __shfl_up_sync(0xffffffffu, li[w], 1);
                        if (lane == pos)      { ld[w] = dv; li[w] = iv; }
                        else if (lane > pos)  { ld[w] = pd; li[w] = pi; }
                    }
                }
            }
        }
    }

    // survivors out (order irrelevant; refine re-sorts)
    #pragma unroll
    for (int w = 0; w < 4; ++w) {
        const size_t m = (size_t)(qb + warp * 4 + w - KNN);
        g_idx[m * KNN + lane] = li[w];
    }
}

// ---------------- phase 2: reference-rounding refine + sort ----------------
// tree sum-of-squares (XLA-GPU row-reduce order): t_l = x_l^2 + x_{l+32}^2
// (mul/add, no fma), then pairwise fold 16,8,4,2,1.
__device__ __forceinline__ float sq_tree_smem(const float* __restrict__ c) {
    float t[32];
    #pragma unroll
    for (int l = 0; l < 32; ++l)
        t[l] = __fadd_rn(__fmul_rn(c[l], c[l]), __fmul_rn(c[l + 32], c[l + 32]));
    #pragma unroll
    for (int l = 0; l < 16; ++l) t[l] = __fadd_rn(t[l], t[l + 16]);
    #pragma unroll
    for (int l = 0; l < 8; ++l)  t[l] = __fadd_rn(t[l], t[l + 8]);
    #pragma unroll
    for (int l = 0; l < 4; ++l)  t[l] = __fadd_rn(t[l], t[l + 4]);
    t[0] = __fadd_rn(t[0], t[2]);
    t[1] = __fadd_rn(t[1], t[3]);
    return __fadd_rn(t[0], t[1]);
}

__global__ __launch_bounds__(NTHREADS) void refine_kernel(const float* __restrict__ X,
                                                          void* __restrict__ out, int mode) {
    __shared__ float qs[RQ * DIM];

    const int tid  = threadIdx.x;
    const int lane = tid & 31;
    const int warp = tid >> 5;
    const size_t m = (size_t)blockIdx.x * RQ + warp;   // query index (grid covers MOUT exactly)

    const float4* X4 = (const float4*)X;
    const int qrow0 = blockIdx.x * RQ + KNN;

    for (int idx = tid; idx < RQ * (DIM / 4); idx += NTHREADS) {
        int row = idx >> 4, c = idx & 15;
        ((float4*)qs)[row * (DIM / 4) + c] = X4[(size_t)(qrow0 + row) * (DIM / 4) + c];
    }
    __syncthreads();

    const float* qrow = &qs[warp * DIM];
    float sqr = sq_tree_smem(qrow);                    // broadcast LDS reads

    int jj = g_idx[m * KNN + lane];

    float cv[DIM];
    const float4* crow = X4 + (size_t)jj * (DIM / 4);
    #pragma unroll
    for (int t = 0; t < DIM / 4; ++t) {
        float4 v = __ldg(&crow[t]);
        cv[4 * t + 0] = v.x; cv[4 * t + 1] = v.y;
        cv[4 * t + 2] = v.z; cv[4 * t + 3] = v.w;
    }
    float sqj = sq_tree_smem(cv);

    // sequential fp32 FMA dot, k ascending (cublas per-thread order)
    float dot = 0.f;
    #pragma unroll
    for (int t = 0; t < DIM; ++t) dot = __fmaf_rn(qrow[t], cv[t], dot);

    float df = fmaxf(__fsub_rn(__fadd_rn(sqr, sqj), __fmul_rn(2.f, dot)), 0.f);

    // bitonic sort across 32 lanes, ascending (df, jj)
    #pragma unroll
    for (int k = 2; k <= 32; k <<= 1) {
        #pragma unroll
        for (int s = k >> 1; s > 0; s >>= 1) {
            float od = __shfl_xor_sync(0xffffffffu, df, s);
            int   oi = __shfl_xor_sync(0xffffffffu, jj, s);
            bool up    = ((lane & k) == 0);
            bool lower = ((lane & s) == 0);
            bool mlt   = (df < od) || (df == od && jj < oi);
            bool take  = (lower == up) ? !mlt : mlt;
            if (take) { df = od; jj = oi; }
        }
    }

    float* of = (float*)out;
    of[m * KNN + lane] = df;
    if (mode == 0) {
        of[(size_t)MOUT * KNN + m * KNN + lane] = (float)jj;
    } else if (mode == 2) {
        long long* oi = (long long*)((char*)out + (size_t)MOUT * KNN * sizeof(float));
        oi[m * KNN + lane] = (long long)jj;
    }
}

extern "C" void kernel_launch(void* const* d_in, const int* in_sizes, int n_in,
                              void* d_out, int out_size) {
    const float* X = (const float*)d_in[0];
    for (int i = 0; i < n_in; ++i) {
        if (in_sizes[i] == NROWS * DIM) { X = (const float*)d_in[i]; break; }
    }

    sq_kernel<<<NROWS / 256, 256>>>(X);
    select_kernel<<<MOUT / QT, NTHREADS>>>(X);

    const int MK = MOUT * KNN;
    int mode;
    if (out_size == MK)            mode = 1;
    else if (out_size == 2 * MK)   mode = 0;
    else                           mode = 2;
    refine_kernel<<<MOUT / RQ, NTHREADS>>>(X, d_out, mode);
}